// round 11
// baseline (speedup 1.0000x reference)
#include <cuda_runtime.h>

// Problem constants
#define T_STEPS 100
#define BATCH   256
#define N_IN    1024
#define N_HID   4096
#define N_OUT   512
#define KHALF   (N_IN / 2)     // gemm1 split-K=2 boundary (validated R9)

#define BETA   0.95f
#define THRESH 1.0f

typedef unsigned long long ull;

// Packed fp32x2 helpers. Each lane is exact IEEE fp32 RN -> bitwise identical
// to two independent scalar fmaf chains.
__device__ __forceinline__ ull dup2(float x) {
    ull r;
    asm("mov.b64 %0, {%1, %1};" : "=l"(r) : "f"(x));
    return r;
}
__device__ __forceinline__ void ffma2(ull& acc, ull a, ull b) {
    asm("fma.rn.f32x2 %0, %1, %2, %0;" : "+l"(acc) : "l"(a), "l"(b));
}
__device__ __forceinline__ float2 unpk(ull v) {
    float2 f;
    asm("mov.b64 {%0, %1}, %2;" : "=f"(f.x), "=f"(f.y) : "l"(v));
    return f;
}

// ---------------------------------------------------------------------------
// RULE: __device__ globals are referenced ONLY inside device code.
// ---------------------------------------------------------------------------
__device__ float g_cur1[(size_t)T_STEPS * BATCH * N_HID];   // 419 MB
__device__ float g_mem1[BATCH * N_HID];
__device__ float g_spk1[BATCH * N_HID];
__device__ float g_mem2[BATCH * N_OUT];

__global__ void init_kernel() {
    int i = blockIdx.x * blockDim.x + threadIdx.x;
    if (i < BATCH * N_HID) g_mem1[i] = 0.0f;
    if (i < BATCH * N_OUT) g_mem2[i] = 0.0f;
}

// ---------------------------------------------------------------------------
// GEMM1: split-K=2, (p0+p1)+b1 (order validated R9), f32x2 inner loop.
// Tile 128x64x16, 256 threads, 8x4 per thread.
// As2 holds duplicated A pairs: As2[k][2m] = As2[k][2m+1] = A[m,k].
// Row strides padded to 16B multiples (260, 68 floats).
// ---------------------------------------------------------------------------
__global__ __launch_bounds__(256) void gemm1_kernel(
    const float* __restrict__ A,     // [25600, N_IN]
    const float* __restrict__ W,     // [N_HID, N_IN]
    const float* __restrict__ bias)  // [N_HID]
{
    const int BK = 16;
    __shared__ float As2[BK][260];   // duplicated, 1040B rows (16B aligned)
    __shared__ float Bs[BK][68];     // 272B rows (16B aligned)

    const int tid = threadIdx.x;
    const int m0 = blockIdx.y * 128;
    const int n0 = blockIdx.x * 64;
    const int tm = (tid >> 4) << 3;   // 0..120
    const int tn = (tid & 15) << 2;   // 0..60

    const int rB  = tid >> 2;         // 0..63
    const int kvB = (tid & 3) << 2;   // 0,4,8,12

    ull accA[8][2], accB[8][2];       // [m][n-pair], lanes = (n, n+1)
    #pragma unroll
    for (int i = 0; i < 8; i++)
        #pragma unroll
        for (int p = 0; p < 2; p++) { accA[i][p] = 0ULL; accB[i][p] = 0ULL; }

    #pragma unroll 1
    for (int half = 0; half < 2; half++) {
        const int kbeg = half ? KHALF : 0;
        const int kend = half ? N_IN : KHALF;

        for (int k0 = kbeg; k0 < kend; k0 += BK) {
            #pragma unroll
            for (int i = 0; i < 2; i++) {
                int l  = tid + i * 256;
                int r  = l >> 2;
                int kv = (l & 3) << 2;
                float4 va = *(const float4*)(A + (size_t)(m0 + r) * N_IN + k0 + kv);
                *(ull*)&As2[kv + 0][2 * r] = dup2(va.x);
                *(ull*)&As2[kv + 1][2 * r] = dup2(va.y);
                *(ull*)&As2[kv + 2][2 * r] = dup2(va.z);
                *(ull*)&As2[kv + 3][2 * r] = dup2(va.w);
            }
            float4 vb = *(const float4*)(W + (size_t)(n0 + rB) * N_IN + k0 + kvB);
            Bs[kvB + 0][rB] = vb.x; Bs[kvB + 1][rB] = vb.y;
            Bs[kvB + 2][rB] = vb.z; Bs[kvB + 3][rB] = vb.w;
            __syncthreads();

            ull (*acc)[2] = half ? accB : accA;
            #pragma unroll
            for (int kk = 0; kk < BK; kk++) {
                ulonglong2 a01 = *(const ulonglong2*)&As2[kk][2 * tm];
                ulonglong2 a23 = *(const ulonglong2*)&As2[kk][2 * tm + 4];
                ulonglong2 a45 = *(const ulonglong2*)&As2[kk][2 * tm + 8];
                ulonglong2 a67 = *(const ulonglong2*)&As2[kk][2 * tm + 12];
                ulonglong2 b   = *(const ulonglong2*)&Bs[kk][tn];
                ffma2(acc[0][0], a01.x, b.x); ffma2(acc[0][1], a01.x, b.y);
                ffma2(acc[1][0], a01.y, b.x); ffma2(acc[1][1], a01.y, b.y);
                ffma2(acc[2][0], a23.x, b.x); ffma2(acc[2][1], a23.x, b.y);
                ffma2(acc[3][0], a23.y, b.x); ffma2(acc[3][1], a23.y, b.y);
                ffma2(acc[4][0], a45.x, b.x); ffma2(acc[4][1], a45.x, b.y);
                ffma2(acc[5][0], a45.y, b.x); ffma2(acc[5][1], a45.y, b.y);
                ffma2(acc[6][0], a67.x, b.x); ffma2(acc[6][1], a67.x, b.y);
                ffma2(acc[7][0], a67.y, b.x); ffma2(acc[7][1], a67.y, b.y);
            }
            __syncthreads();
        }
    }

    // epilogue: (p0 + p1) + bias, per scalar lane (order identical to R9)
    float bv[4];
    *(float4*)&bv[0] = *(const float4*)&bias[n0 + tn];

    #pragma unroll
    for (int i = 0; i < 8; i++) {
        float2 a0 = unpk(accA[i][0]), a1 = unpk(accA[i][1]);
        float2 b0 = unpk(accB[i][0]), b1 = unpk(accB[i][1]);
        float o[4];
        o[0] = __fadd_rn(__fadd_rn(a0.x, b0.x), bv[0]);
        o[1] = __fadd_rn(__fadd_rn(a0.y, b0.y), bv[1]);
        o[2] = __fadd_rn(__fadd_rn(a1.x, b1.x), bv[2]);
        o[3] = __fadd_rn(__fadd_rn(a1.y, b1.y), bv[3]);
        *(float4*)(g_cur1 + (size_t)(m0 + tm + i) * N_HID + n0 + tn) =
            make_float4(o[0], o[1], o[2], o[3]);
    }
}

// ---------------------------------------------------------------------------
// LIF update (de-contracted; validated R9)
// ---------------------------------------------------------------------------
__device__ __forceinline__ void lif_update(float m, float c, float& nm, float& sp) {
    float t0 = __fmul_rn(BETA, m);
    float t1 = __fadd_rn(t0, c);
    float rst = (m > THRESH) ? THRESH : 0.0f;
    nm = __fsub_rn(t1, rst);
    sp = (nm > THRESH) ? 1.0f : 0.0f;
}

__global__ __launch_bounds__(256) void step1_kernel(int t) {
    const float* cur1_t = g_cur1 + (size_t)t * BATCH * N_HID;
    int i = blockIdx.x * blockDim.x + threadIdx.x;
    float4 c = ((const float4*)cur1_t)[i];
    float4 m = ((const float4*)g_mem1)[i];
    float4 nm, sp;
    lif_update(m.x, c.x, nm.x, sp.x);
    lif_update(m.y, c.y, nm.y, sp.y);
    lif_update(m.z, c.z, nm.z, sp.z);
    lif_update(m.w, c.w, nm.w, sp.w);
    ((float4*)g_mem1)[i] = nm;
    ((float4*)g_spk1)[i] = sp;
}

// ---------------------------------------------------------------------------
// GEMM2 + fused LIF-2, f32x2 inner loop (per-output chain order unchanged:
// single ascending-k chain, add.rn(acc,b2), LIF — bitwise == R10).
// Tile 32x32, BK=32, 256 threads, 2x2/thread. grid (16,8) = 128 blocks.
// As2 duplicated pairs, padded row 68 floats (272B, 16B aligned).
// ---------------------------------------------------------------------------
__global__ __launch_bounds__(256) void gemm2_fused_kernel(
    const float* __restrict__ W2,    // [N_OUT, N_HID]
    const float* __restrict__ b2,    // [N_OUT]
    float* __restrict__ out_spk,     // [B, N_OUT] slice for this t
    float* __restrict__ out_mem)     // [B, N_OUT] slice for this t
{
    const int BK = 32;
    __shared__ float As2[BK][68];  // [k][2m dup]
    __shared__ float Bs[BK][32];   // [k][n]

    const int tid = threadIdx.x;
    const int n0 = blockIdx.x * 32;
    const int m0 = blockIdx.y * 32;
    const int tm = (tid >> 4) << 1;   // 0..30
    const int tn = (tid & 15) << 1;   // 0..30
    const int lr = tid >> 3;          // 0..31
    const int lk = (tid & 7) << 2;    // 0,4,...,28

    // acc pairs over n: accP0 = (acc[m][n], acc[m][n+1]); accP1 = row m+1
    ull accP0 = 0ULL, accP1 = 0ULL;

    const float* aptr = g_spk1 + (size_t)(m0 + lr) * N_HID + lk;
    const float* bptr = W2     + (size_t)(n0 + lr) * N_HID + lk;

    float4 va = *(const float4*)(aptr);
    float4 vb = *(const float4*)(bptr);

    for (int k0 = 0; k0 < N_HID; k0 += BK) {
        *(ull*)&As2[lk + 0][2 * lr] = dup2(va.x);
        *(ull*)&As2[lk + 1][2 * lr] = dup2(va.y);
        *(ull*)&As2[lk + 2][2 * lr] = dup2(va.z);
        *(ull*)&As2[lk + 3][2 * lr] = dup2(va.w);
        Bs[lk + 0][lr] = vb.x; Bs[lk + 1][lr] = vb.y;
        Bs[lk + 2][lr] = vb.z; Bs[lk + 3][lr] = vb.w;
        __syncthreads();

        if (k0 + BK < N_HID) {
            va = *(const float4*)(aptr + k0 + BK);
            vb = *(const float4*)(bptr + k0 + BK);
        }

        #pragma unroll
        for (int kk = 0; kk < BK; kk++) {
            ulonglong2 a = *(const ulonglong2*)&As2[kk][2 * tm]; // dup(m), dup(m+1)
            ull b = *(const ull*)&Bs[kk][tn];                    // (w_n, w_n+1)
            ffma2(accP0, a.x, b);
            ffma2(accP1, a.y, b);
        }
        __syncthreads();
    }

    float2 r0 = unpk(accP0);   // acc[m][n], acc[m][n+1]
    float2 r1 = unpk(accP1);   // acc[m+1][n], acc[m+1][n+1]

    const int mg = m0 + tm;
    const int ng = n0 + tn;
    const float bbx = b2[ng];
    const float bby = b2[ng + 1];

    {
        float c = __fadd_rn(r0.x, bbx);
        float mo = g_mem2[(size_t)mg * N_OUT + ng];
        float nm, sp; lif_update(mo, c, nm, sp);
        g_mem2[(size_t)mg * N_OUT + ng] = nm;
        out_spk[(size_t)mg * N_OUT + ng] = sp;
        out_mem[(size_t)mg * N_OUT + ng] = nm;
    }
    {
        float c = __fadd_rn(r0.y, bby);
        float mo = g_mem2[(size_t)mg * N_OUT + ng + 1];
        float nm, sp; lif_update(mo, c, nm, sp);
        g_mem2[(size_t)mg * N_OUT + ng + 1] = nm;
        out_spk[(size_t)mg * N_OUT + ng + 1] = sp;
        out_mem[(size_t)mg * N_OUT + ng + 1] = nm;
    }
    {
        float c = __fadd_rn(r1.x, bbx);
        float mo = g_mem2[(size_t)(mg + 1) * N_OUT + ng];
        float nm, sp; lif_update(mo, c, nm, sp);
        g_mem2[(size_t)(mg + 1) * N_OUT + ng] = nm;
        out_spk[(size_t)(mg + 1) * N_OUT + ng] = sp;
        out_mem[(size_t)(mg + 1) * N_OUT + ng] = nm;
    }
    {
        float c = __fadd_rn(r1.y, bby);
        float mo = g_mem2[(size_t)(mg + 1) * N_OUT + ng + 1];
        float nm, sp; lif_update(mo, c, nm, sp);
        g_mem2[(size_t)(mg + 1) * N_OUT + ng + 1] = nm;
        out_spk[(size_t)(mg + 1) * N_OUT + ng + 1] = sp;
        out_mem[(size_t)(mg + 1) * N_OUT + ng + 1] = nm;
    }
}

// ---------------------------------------------------------------------------
// Launch — no __device__ symbol addresses taken on the host.
// ---------------------------------------------------------------------------
extern "C" void kernel_launch(void* const* d_in, const int* in_sizes, int n_in,
                              void* d_out, int out_size) {
    const float* x  = (const float*)d_in[0];
    const float* W1 = (const float*)d_in[1];
    const float* b1 = (const float*)d_in[2];
    const float* W2 = (const float*)d_in[3];
    const float* b2 = (const float*)d_in[4];
    float* out = (float*)d_out;

    init_kernel<<<(BATCH * N_HID + 255) / 256, 256>>>();

    {
        dim3 grid(N_HID / 64, (T_STEPS * BATCH) / 128);   // (64, 200)
        gemm1_kernel<<<grid, 256>>>(x, W1, b1);
    }

    float* out_spk_base = out;
    float* out_mem_base = out + (size_t)T_STEPS * BATCH * N_OUT;

    for (int t = 0; t < T_STEPS; t++) {
        step1_kernel<<<(BATCH * N_HID / 4) / 256, 256>>>(t);

        dim3 grid2(N_OUT / 32, BATCH / 32);               // (16, 8) = 128 blocks
        gemm2_fused_kernel<<<grid2, 256>>>(
            W2, b2,
            out_spk_base + (size_t)t * BATCH * N_OUT,
            out_mem_base + (size_t)t * BATCH * N_OUT);
    }
}

// round 12
// speedup vs baseline: 2.7906x; 2.7906x over previous
#include <cuda_runtime.h>

// Problem constants
#define T_STEPS 100
#define BATCH   256
#define N_IN    1024
#define N_HID   4096
#define N_OUT   512
#define KHALF   (N_IN / 2)     // gemm1 split-K=2 boundary (validated R9)

#define BETA   0.95f
#define THRESH 1.0f

// ---------------------------------------------------------------------------
// RULE: __device__ globals are referenced ONLY inside device code.
// ---------------------------------------------------------------------------
__device__ float g_cur1[(size_t)T_STEPS * BATCH * N_HID];   // 419 MB
__device__ float g_mem1[BATCH * N_HID];
__device__ float g_mem2[BATCH * N_OUT];
__device__ float g_W2T[(size_t)N_HID * N_OUT];              // 8 MB transposed W2
__device__ int   g_idx[BATCH * N_HID];                      // per-row spike indices
__device__ int   g_cnt[BATCH];

__global__ void init_kernel() {
    int i = blockIdx.x * blockDim.x + threadIdx.x;
    if (i < BATCH * N_HID) g_mem1[i] = 0.0f;
    if (i < BATCH * N_OUT) g_mem2[i] = 0.0f;
}

// ---------------------------------------------------------------------------
// One-time transpose: g_W2T[k][n] = W2[n][k]. Tiled 32x32 via smem.
// ---------------------------------------------------------------------------
__global__ __launch_bounds__(256) void transpose_w2_kernel(const float* __restrict__ W2) {
    __shared__ float tile[32][33];
    const int k0 = blockIdx.x * 32;
    const int n0 = blockIdx.y * 32;
    const int tx = threadIdx.x & 31;
    const int ty = threadIdx.x >> 5;   // 0..7
    #pragma unroll
    for (int i = 0; i < 4; i++)
        tile[ty + i * 8][tx] = W2[(size_t)(n0 + ty + i * 8) * N_HID + k0 + tx];
    __syncthreads();
    #pragma unroll
    for (int i = 0; i < 4; i++)
        g_W2T[(size_t)(k0 + ty + i * 8) * N_OUT + n0 + tx] = tile[tx][ty + i * 8];
}

// ---------------------------------------------------------------------------
// GEMM1 (VERBATIM R9/R10 scalar, bitwise-validated): split-K=2, (p0+p1)+b1.
// Tile 128x64x16, 256 threads, 8x4 per thread.
// ---------------------------------------------------------------------------
__global__ __launch_bounds__(256) void gemm1_kernel(
    const float* __restrict__ A,     // [25600, N_IN]
    const float* __restrict__ W,     // [N_HID, N_IN]
    const float* __restrict__ bias)  // [N_HID]
{
    const int BK = 16;
    __shared__ float As[BK][128];
    __shared__ float Bs[BK][64];

    const int tid = threadIdx.x;
    const int m0 = blockIdx.y * 128;
    const int n0 = blockIdx.x * 64;
    const int tm = (tid >> 4) << 3;
    const int tn = (tid & 15) << 2;

    const int rB  = tid >> 2;
    const int kvB = (tid & 3) << 2;

    float accA[8][4], accB[8][4];
    #pragma unroll
    for (int i = 0; i < 8; i++)
        #pragma unroll
        for (int j = 0; j < 4; j++) { accA[i][j] = 0.0f; accB[i][j] = 0.0f; }

    for (int k0 = 0; k0 < KHALF; k0 += BK) {
        #pragma unroll
        for (int i = 0; i < 2; i++) {
            int l  = tid + i * 256;
            int r  = l >> 2;
            int kv = (l & 3) << 2;
            float4 va = *(const float4*)(A + (size_t)(m0 + r) * N_IN + k0 + kv);
            As[kv + 0][r] = va.x; As[kv + 1][r] = va.y;
            As[kv + 2][r] = va.z; As[kv + 3][r] = va.w;
        }
        float4 vb = *(const float4*)(W + (size_t)(n0 + rB) * N_IN + k0 + kvB);
        Bs[kvB + 0][rB] = vb.x; Bs[kvB + 1][rB] = vb.y;
        Bs[kvB + 2][rB] = vb.z; Bs[kvB + 3][rB] = vb.w;
        __syncthreads();

        #pragma unroll
        for (int kk = 0; kk < BK; kk++) {
            float a[8], b[4];
            *(float4*)&a[0] = *(const float4*)&As[kk][tm];
            *(float4*)&a[4] = *(const float4*)&As[kk][tm + 4];
            *(float4*)&b[0] = *(const float4*)&Bs[kk][tn];
            #pragma unroll
            for (int i = 0; i < 8; i++)
                #pragma unroll
                for (int j = 0; j < 4; j++)
                    accA[i][j] = fmaf(a[i], b[j], accA[i][j]);
        }
        __syncthreads();
    }

    for (int k0 = KHALF; k0 < N_IN; k0 += BK) {
        #pragma unroll
        for (int i = 0; i < 2; i++) {
            int l  = tid + i * 256;
            int r  = l >> 2;
            int kv = (l & 3) << 2;
            float4 va = *(const float4*)(A + (size_t)(m0 + r) * N_IN + k0 + kv);
            As[kv + 0][r] = va.x; As[kv + 1][r] = va.y;
            As[kv + 2][r] = va.z; As[kv + 3][r] = va.w;
        }
        float4 vb = *(const float4*)(W + (size_t)(n0 + rB) * N_IN + k0 + kvB);
        Bs[kvB + 0][rB] = vb.x; Bs[kvB + 1][rB] = vb.y;
        Bs[kvB + 2][rB] = vb.z; Bs[kvB + 3][rB] = vb.w;
        __syncthreads();

        #pragma unroll
        for (int kk = 0; kk < BK; kk++) {
            float a[8], b[4];
            *(float4*)&a[0] = *(const float4*)&As[kk][tm];
            *(float4*)&a[4] = *(const float4*)&As[kk][tm + 4];
            *(float4*)&b[0] = *(const float4*)&Bs[kk][tn];
            #pragma unroll
            for (int i = 0; i < 8; i++)
                #pragma unroll
                for (int j = 0; j < 4; j++)
                    accB[i][j] = fmaf(a[i], b[j], accB[i][j]);
        }
        __syncthreads();
    }

    float bv[4];
    *(float4*)&bv[0] = *(const float4*)&bias[n0 + tn];

    #pragma unroll
    for (int i = 0; i < 8; i++) {
        float o[4];
        #pragma unroll
        for (int j = 0; j < 4; j++)
            o[j] = __fadd_rn(__fadd_rn(accA[i][j], accB[i][j]), bv[j]);
        *(float4*)(g_cur1 + (size_t)(m0 + tm + i) * N_HID + n0 + tn) =
            make_float4(o[0], o[1], o[2], o[3]);
    }
}

// ---------------------------------------------------------------------------
// LIF update (de-contracted; validated R9)
// ---------------------------------------------------------------------------
__device__ __forceinline__ void lif_update(float m, float c, float& nm, float& sp) {
    float t0 = __fmul_rn(BETA, m);
    float t1 = __fadd_rn(t0, c);
    float rst = (m > THRESH) ? THRESH : 0.0f;
    nm = __fsub_rn(t1, rst);
    sp = (nm > THRESH) ? 1.0f : 0.0f;
}

// ---------------------------------------------------------------------------
// Step 1 + ordered compaction. One block per batch row m (256 blocks x 256 thr).
// LIF arithmetic identical to validated step1. Emits ascending-k index list of
// spiking neurons (pass-major, tid-major, element-major == ascending k).
// ---------------------------------------------------------------------------
__global__ __launch_bounds__(256) void step1_compact_kernel(int t) {
    const int m = blockIdx.x;
    const int tid = threadIdx.x;
    const int lane = tid & 31;
    const int wid = tid >> 5;

    __shared__ int warp_tot[8];
    __shared__ int warp_base[8];
    __shared__ int pass_base;

    if (tid == 0) pass_base = 0;
    __syncthreads();

    const float* cur = g_cur1 + (size_t)t * BATCH * N_HID + (size_t)m * N_HID;
    float* memr = g_mem1 + (size_t)m * N_HID;
    int* idxrow = g_idx + (size_t)m * N_HID;

    #pragma unroll 1
    for (int pass = 0; pass < 4; pass++) {
        const int i0 = pass * 1024 + tid * 4;
        float4 c = *(const float4*)(cur + i0);
        float4 mm = *(const float4*)(memr + i0);
        float4 nm; float sp[4];
        lif_update(mm.x, c.x, nm.x, sp[0]);
        lif_update(mm.y, c.y, nm.y, sp[1]);
        lif_update(mm.z, c.z, nm.z, sp[2]);
        lif_update(mm.w, c.w, nm.w, sp[3]);
        *(float4*)(memr + i0) = nm;

        int bits = (sp[0] > 0.0f ? 1 : 0) | (sp[1] > 0.0f ? 2 : 0)
                 | (sp[2] > 0.0f ? 4 : 0) | (sp[3] > 0.0f ? 8 : 0);
        int cnt = __popc(bits);

        // warp inclusive scan of cnt
        int pre = cnt;
        #pragma unroll
        for (int d = 1; d < 32; d <<= 1) {
            int v = __shfl_up_sync(0xFFFFFFFFu, pre, d);
            if (lane >= d) pre += v;
        }
        int excl = pre - cnt;
        if (lane == 31) warp_tot[wid] = pre;
        __syncthreads();

        if (tid == 0) {
            int s = pass_base;
            #pragma unroll
            for (int w = 0; w < 8; w++) { warp_base[w] = s; s += warp_tot[w]; }
            pass_base = s;
        }
        __syncthreads();

        int off = warp_base[wid] + excl;
        #pragma unroll
        for (int j = 0; j < 4; j++)
            if ((bits >> j) & 1) idxrow[off++] = i0 + j;
        __syncthreads();   // protect warp_tot reuse next pass
    }

    if (tid == 0) g_cnt[m] = pass_base;
}

// ---------------------------------------------------------------------------
// Sparse GEMM2 + fused LIF-2. One block per row m (256 blocks x 256 threads).
// cur2[m,n] = sum over spiking k (ascending) of W2T[k][n]  — bitwise identical
// to the dense ascending-k fmaf chain (fmaf(0,w,acc)==acc; fmaf(1,w,acc)==
// fadd(acc,w); acc never becomes -0 in RN). Then add.rn(acc,b2), LIF, write.
// ---------------------------------------------------------------------------
__global__ __launch_bounds__(256) void gemm2_sparse_kernel(
    const float* __restrict__ b2,
    float* __restrict__ out_spk,
    float* __restrict__ out_mem)
{
    const int m = blockIdx.x;
    const int tid = threadIdx.x;
    const int n2 = tid * 2;          // each thread owns columns n2, n2+1

    __shared__ int sidx[1024];

    const int cnt = g_cnt[m];
    const int* idxrow = g_idx + (size_t)m * N_HID;

    float accx = 0.0f, accy = 0.0f;

    for (int base = 0; base < cnt; base += 1024) {
        const int ch = min(1024, cnt - base);
        __syncthreads();
        for (int j = tid; j < ch; j += 256) sidx[j] = idxrow[base + j];
        __syncthreads();

        int j = 0;
        for (; j + 4 <= ch; j += 4) {
            int k0 = sidx[j], k1 = sidx[j + 1], k2 = sidx[j + 2], k3 = sidx[j + 3];
            float2 w0 = *(const float2*)(g_W2T + (size_t)k0 * N_OUT + n2);
            float2 w1 = *(const float2*)(g_W2T + (size_t)k1 * N_OUT + n2);
            float2 w2 = *(const float2*)(g_W2T + (size_t)k2 * N_OUT + n2);
            float2 w3 = *(const float2*)(g_W2T + (size_t)k3 * N_OUT + n2);
            accx = __fadd_rn(accx, w0.x); accy = __fadd_rn(accy, w0.y);
            accx = __fadd_rn(accx, w1.x); accy = __fadd_rn(accy, w1.y);
            accx = __fadd_rn(accx, w2.x); accy = __fadd_rn(accy, w2.y);
            accx = __fadd_rn(accx, w3.x); accy = __fadd_rn(accy, w3.y);
        }
        for (; j < ch; j++) {
            int k = sidx[j];
            float2 w = *(const float2*)(g_W2T + (size_t)k * N_OUT + n2);
            accx = __fadd_rn(accx, w.x); accy = __fadd_rn(accy, w.y);
        }
    }

    // fused step2 epilogue
    float2 bb = *(const float2*)(b2 + n2);
    float cx = __fadd_rn(accx, bb.x);
    float cy = __fadd_rn(accy, bb.y);
    float2 mo = *(const float2*)(g_mem2 + (size_t)m * N_OUT + n2);
    float nmx, nmy, spx, spy;
    lif_update(mo.x, cx, nmx, spx);
    lif_update(mo.y, cy, nmy, spy);
    *(float2*)(g_mem2 + (size_t)m * N_OUT + n2) = make_float2(nmx, nmy);
    *(float2*)(out_spk + (size_t)m * N_OUT + n2) = make_float2(spx, spy);
    *(float2*)(out_mem + (size_t)m * N_OUT + n2) = make_float2(nmx, nmy);
}

// ---------------------------------------------------------------------------
// Launch — no __device__ symbol addresses taken on the host.
// ---------------------------------------------------------------------------
extern "C" void kernel_launch(void* const* d_in, const int* in_sizes, int n_in,
                              void* d_out, int out_size) {
    const float* x  = (const float*)d_in[0];
    const float* W1 = (const float*)d_in[1];
    const float* b1 = (const float*)d_in[2];
    const float* W2 = (const float*)d_in[3];
    const float* b2 = (const float*)d_in[4];
    float* out = (float*)d_out;

    init_kernel<<<(BATCH * N_HID + 255) / 256, 256>>>();

    {
        dim3 gT(N_HID / 32, N_OUT / 32);                  // (128, 16)
        transpose_w2_kernel<<<gT, 256>>>(W2);
    }
    {
        dim3 grid(N_HID / 64, (T_STEPS * BATCH) / 128);   // (64, 200)
        gemm1_kernel<<<grid, 256>>>(x, W1, b1);
    }

    float* out_spk_base = out;
    float* out_mem_base = out + (size_t)T_STEPS * BATCH * N_OUT;

    for (int t = 0; t < T_STEPS; t++) {
        step1_compact_kernel<<<BATCH, 256>>>(t);
        gemm2_sparse_kernel<<<BATCH, 256>>>(
            b2,
            out_spk_base + (size_t)t * BATCH * N_OUT,
            out_mem_base + (size_t)t * BATCH * N_OUT);
    }
}

// round 13
// speedup vs baseline: 3.1798x; 1.1395x over previous
#include <cuda_runtime.h>

// Problem constants
#define T_STEPS 100
#define BATCH   256
#define N_IN    1024
#define N_HID   4096
#define N_OUT   512
#define KHALF   512            // gemm1 split-K=2 boundary (validated R9)

#define BETA   0.95f
#define THRESH 1.0f

typedef unsigned long long ull;

// Packed fp32x2: each lane is an independent IEEE fp32 RN FMA -> a packed
// accumulator holds two independent scalar fmaf chains, bitwise identical.
__device__ __forceinline__ ull dup2(float x) {
    ull r; asm("mov.b64 %0, {%1, %1};" : "=l"(r) : "f"(x)); return r;
}
__device__ __forceinline__ void ffma2(ull& acc, ull a, ull b) {
    asm("fma.rn.f32x2 %0, %1, %2, %0;" : "+l"(acc) : "l"(a), "l"(b));
}
__device__ __forceinline__ float2 unpk(ull v) {
    float2 f; asm("mov.b64 {%0, %1}, %2;" : "=f"(f.x), "=f"(f.y) : "l"(v)); return f;
}

// ---------------------------------------------------------------------------
// RULE: __device__ globals are referenced ONLY inside device code.
// ---------------------------------------------------------------------------
__device__ float g_cur1[(size_t)T_STEPS * BATCH * N_HID];   // 419 MB
__device__ float g_mem1[BATCH * N_HID];
__device__ float g_mem2[BATCH * N_OUT];
__device__ float g_W2T[(size_t)N_HID * N_OUT];              // 8 MB transposed W2

__global__ void init_kernel() {
    int i = blockIdx.x * blockDim.x + threadIdx.x;
    if (i < BATCH * N_HID) g_mem1[i] = 0.0f;
    if (i < BATCH * N_OUT) g_mem2[i] = 0.0f;
}

// ---------------------------------------------------------------------------
// One-time transpose: g_W2T[k][n] = W2[n][k].
// ---------------------------------------------------------------------------
__global__ __launch_bounds__(256) void transpose_w2_kernel(const float* __restrict__ W2) {
    __shared__ float tile[32][33];
    const int k0 = blockIdx.x * 32;
    const int n0 = blockIdx.y * 32;
    const int tx = threadIdx.x & 31;
    const int ty = threadIdx.x >> 5;
    #pragma unroll
    for (int i = 0; i < 4; i++)
        tile[ty + i * 8][tx] = W2[(size_t)(n0 + ty + i * 8) * N_HID + k0 + tx];
    __syncthreads();
    #pragma unroll
    for (int i = 0; i < 4; i++)
        g_W2T[(size_t)(k0 + ty + i * 8) * N_OUT + n0 + tx] = tile[tx][ty + i * 8];
}

// ---------------------------------------------------------------------------
// GEMM1: split-K=2, (p0+p1)+b1 (order validated R9), packed f32x2 math.
// 128x128 tile, BK=16, 256 threads, 8m x 8n per thread.
// smem layout per k-row (132-float padded): element x at
//   off(x) = ((x & 4) << 4) + ((x >> 3) << 2) + (x & 3)
// so thread's 8 values = two contiguous 16B chunks at 4*t and 64 + 4*t.
// Accumulators are m-pair packed: acc[p][n] = (C[m+2p][n], C[m+2p+1][n]).
// ---------------------------------------------------------------------------
#define G1_BK  16
#define G1_ROW 132

__device__ __forceinline__ int g1_off(int x) {
    return ((x & 4) << 4) + ((x >> 3) << 2) + (x & 3);
}

__global__ __launch_bounds__(256) void gemm1_kernel(
    const float* __restrict__ A,     // [25600, N_IN]
    const float* __restrict__ W,     // [N_HID, N_IN]
    const float* __restrict__ bias)  // [N_HID]
{
    __shared__ float As[G1_BK * G1_ROW];
    __shared__ float Bs[G1_BK * G1_ROW];

    const int tid = threadIdx.x;
    const int m0 = blockIdx.y * 128;
    const int n0 = blockIdx.x * 128;
    const int tm = tid >> 4;          // 0..15 -> rows m0+8*tm..+7
    const int tn = tid & 15;          // 0..15 -> cols n0+8*tn..+7

    // Per-thread load coordinates (two float4 loads per array per tile)
    int lr[2], lkv[2];
    #pragma unroll
    for (int i = 0; i < 2; i++) {
        int l = tid + (i << 8);
        lr[i]  = l >> 2;              // 0..127
        lkv[i] = (l & 3) << 2;        // 0,4,8,12
    }

    ull accA[4][8], accB[4][8];
    #pragma unroll
    for (int p = 0; p < 4; p++)
        #pragma unroll
        for (int n = 0; n < 8; n++) { accA[p][n] = 0ULL; accB[p][n] = 0ULL; }

    float4 pa[2], pb[2];
    #pragma unroll
    for (int i = 0; i < 2; i++) {
        pa[i] = *(const float4*)(A + (size_t)(m0 + lr[i]) * N_IN + lkv[i]);
        pb[i] = *(const float4*)(W + (size_t)(n0 + lr[i]) * N_IN + lkv[i]);
    }

#define G1_TILE(ACC, K0, LAST_K)                                              \
    {                                                                         \
        _Pragma("unroll")                                                     \
        for (int i = 0; i < 2; i++) {                                         \
            int r = lr[i], kv = lkv[i];                                       \
            As[(kv + 0) * G1_ROW + g1_off(r)] = pa[i].x;                      \
            As[(kv + 1) * G1_ROW + g1_off(r)] = pa[i].y;                      \
            As[(kv + 2) * G1_ROW + g1_off(r)] = pa[i].z;                      \
            As[(kv + 3) * G1_ROW + g1_off(r)] = pa[i].w;                      \
            Bs[(kv + 0) * G1_ROW + g1_off(r)] = pb[i].x;                      \
            Bs[(kv + 1) * G1_ROW + g1_off(r)] = pb[i].y;                      \
            Bs[(kv + 2) * G1_ROW + g1_off(r)] = pb[i].z;                      \
            Bs[(kv + 3) * G1_ROW + g1_off(r)] = pb[i].w;                      \
        }                                                                     \
        __syncthreads();                                                      \
        if ((K0) + G1_BK < (LAST_K)) {                                        \
            _Pragma("unroll")                                                 \
            for (int i = 0; i < 2; i++) {                                     \
                pa[i] = *(const float4*)(A + (size_t)(m0 + lr[i]) * N_IN + (K0) + G1_BK + lkv[i]); \
                pb[i] = *(const float4*)(W + (size_t)(n0 + lr[i]) * N_IN + (K0) + G1_BK + lkv[i]); \
            }                                                                 \
        }                                                                     \
        _Pragma("unroll")                                                     \
        for (int kk = 0; kk < G1_BK; kk++) {                                  \
            const float* ak = As + kk * G1_ROW;                               \
            const float* bk = Bs + kk * G1_ROW;                               \
            ulonglong2 A0 = *(const ulonglong2*)(ak + 4 * tm);                \
            ulonglong2 A1 = *(const ulonglong2*)(ak + 64 + 4 * tm);           \
            float4 b0 = *(const float4*)(bk + 4 * tn);                        \
            float4 b1 = *(const float4*)(bk + 64 + 4 * tn);                   \
            ull bd0 = dup2(b0.x), bd1 = dup2(b0.y), bd2 = dup2(b0.z), bd3 = dup2(b0.w); \
            ull bd4 = dup2(b1.x), bd5 = dup2(b1.y), bd6 = dup2(b1.z), bd7 = dup2(b1.w); \
            ffma2(ACC[0][0], A0.x, bd0); ffma2(ACC[0][1], A0.x, bd1);         \
            ffma2(ACC[0][2], A0.x, bd2); ffma2(ACC[0][3], A0.x, bd3);         \
            ffma2(ACC[0][4], A0.x, bd4); ffma2(ACC[0][5], A0.x, bd5);         \
            ffma2(ACC[0][6], A0.x, bd6); ffma2(ACC[0][7], A0.x, bd7);         \
            ffma2(ACC[1][0], A0.y, bd0); ffma2(ACC[1][1], A0.y, bd1);         \
            ffma2(ACC[1][2], A0.y, bd2); ffma2(ACC[1][3], A0.y, bd3);         \
            ffma2(ACC[1][4], A0.y, bd4); ffma2(ACC[1][5], A0.y, bd5);         \
            ffma2(ACC[1][6], A0.y, bd6); ffma2(ACC[1][7], A0.y, bd7);         \
            ffma2(ACC[2][0], A1.x, bd0); ffma2(ACC[2][1], A1.x, bd1);         \
            ffma2(ACC[2][2], A1.x, bd2); ffma2(ACC[2][3], A1.x, bd3);         \
            ffma2(ACC[2][4], A1.x, bd4); ffma2(ACC[2][5], A1.x, bd5);         \
            ffma2(ACC[2][6], A1.x, bd6); ffma2(ACC[2][7], A1.x, bd7);         \
            ffma2(ACC[3][0], A1.y, bd0); ffma2(ACC[3][1], A1.y, bd1);         \
            ffma2(ACC[3][2], A1.y, bd2); ffma2(ACC[3][3], A1.y, bd3);         \
            ffma2(ACC[3][4], A1.y, bd4); ffma2(ACC[3][5], A1.y, bd5);         \
            ffma2(ACC[3][6], A1.y, bd6); ffma2(ACC[3][7], A1.y, bd7);         \
        }                                                                     \
        __syncthreads();                                                      \
    }

    for (int k0 = 0; k0 < KHALF; k0 += G1_BK)      G1_TILE(accA, k0, N_IN)
    for (int k0 = KHALF; k0 < N_IN; k0 += G1_BK)   G1_TILE(accB, k0, N_IN)
#undef G1_TILE

    // Epilogue: per scalar lane (p0 + p1) + bias — identical order to R9.
    float bv[8];
    *(float4*)&bv[0] = *(const float4*)&bias[n0 + 8 * tn];
    *(float4*)&bv[4] = *(const float4*)&bias[n0 + 8 * tn + 4];

    #pragma unroll
    for (int p = 0; p < 4; p++) {
        float o0[8], o1[8];
        #pragma unroll
        for (int n = 0; n < 8; n++) {
            float2 a = unpk(accA[p][n]);
            float2 b = unpk(accB[p][n]);
            o0[n] = __fadd_rn(__fadd_rn(a.x, b.x), bv[n]);   // row m+2p
            o1[n] = __fadd_rn(__fadd_rn(a.y, b.y), bv[n]);   // row m+2p+1
        }
        float* c0 = g_cur1 + (size_t)(m0 + 8 * tm + 2 * p) * N_HID + n0 + 8 * tn;
        float* c1 = c0 + N_HID;
        *(float4*)(c0)     = make_float4(o0[0], o0[1], o0[2], o0[3]);
        *(float4*)(c0 + 4) = make_float4(o0[4], o0[5], o0[6], o0[7]);
        *(float4*)(c1)     = make_float4(o1[0], o1[1], o1[2], o1[3]);
        *(float4*)(c1 + 4) = make_float4(o1[4], o1[5], o1[6], o1[7]);
    }
}

// ---------------------------------------------------------------------------
// LIF update (de-contracted; validated R9)
// ---------------------------------------------------------------------------
__device__ __forceinline__ void lif_update(float m, float c, float& nm, float& sp) {
    float t0 = __fmul_rn(BETA, m);
    float t1 = __fadd_rn(t0, c);
    float rst = (m > THRESH) ? THRESH : 0.0f;
    nm = __fsub_rn(t1, rst);
    sp = (nm > THRESH) ? 1.0f : 0.0f;
}

// ---------------------------------------------------------------------------
// Fused per-timestep kernel: one block per batch row m.
// Phase 1: LIF layer-1 + ordered compaction (indices in smem — no gmem trip).
// Phase 2: sparse gather-sum of W2T rows (ascending k == bitwise dense chain),
//          then add.rn(acc,b2), LIF layer-2, write spk2+mem2.
// All arithmetic identical to R12's step1_compact + gemm2_sparse kernels.
// ---------------------------------------------------------------------------
__global__ __launch_bounds__(256) void step_fused_kernel(
    int t,
    const float* __restrict__ b2,
    float* __restrict__ out_spk,
    float* __restrict__ out_mem)
{
    const int m = blockIdx.x;
    const int tid = threadIdx.x;
    const int lane = tid & 31;
    const int wid = tid >> 5;

    __shared__ int sidx[N_HID];
    __shared__ int warp_tot[8];
    __shared__ int warp_base[8];
    __shared__ int pass_base;

    if (tid == 0) pass_base = 0;
    __syncthreads();

    const float* cur = g_cur1 + (size_t)t * BATCH * N_HID + (size_t)m * N_HID;
    float* memr = g_mem1 + (size_t)m * N_HID;

    #pragma unroll 1
    for (int pass = 0; pass < 4; pass++) {
        const int i0 = pass * 1024 + tid * 4;
        float4 c = *(const float4*)(cur + i0);
        float4 mm = *(const float4*)(memr + i0);
        float4 nm; float sp[4];
        lif_update(mm.x, c.x, nm.x, sp[0]);
        lif_update(mm.y, c.y, nm.y, sp[1]);
        lif_update(mm.z, c.z, nm.z, sp[2]);
        lif_update(mm.w, c.w, nm.w, sp[3]);
        *(float4*)(memr + i0) = nm;

        int bits = (sp[0] > 0.0f ? 1 : 0) | (sp[1] > 0.0f ? 2 : 0)
                 | (sp[2] > 0.0f ? 4 : 0) | (sp[3] > 0.0f ? 8 : 0);
        int cnt = __popc(bits);

        int pre = cnt;
        #pragma unroll
        for (int d = 1; d < 32; d <<= 1) {
            int v = __shfl_up_sync(0xFFFFFFFFu, pre, d);
            if (lane >= d) pre += v;
        }
        int excl = pre - cnt;
        if (lane == 31) warp_tot[wid] = pre;
        __syncthreads();

        if (tid == 0) {
            int s = pass_base;
            #pragma unroll
            for (int w = 0; w < 8; w++) { warp_base[w] = s; s += warp_tot[w]; }
            pass_base = s;
        }
        __syncthreads();

        int off = warp_base[wid] + excl;
        #pragma unroll
        for (int j = 0; j < 4; j++)
            if ((bits >> j) & 1) sidx[off++] = i0 + j;
        __syncthreads();
    }

    const int cnt = pass_base;
    const int n2 = tid * 2;

    float accx = 0.0f, accy = 0.0f;
    int j = 0;
    for (; j + 4 <= cnt; j += 4) {
        int k0 = sidx[j], k1 = sidx[j + 1], k2 = sidx[j + 2], k3 = sidx[j + 3];
        float2 w0 = *(const float2*)(g_W2T + (size_t)k0 * N_OUT + n2);
        float2 w1 = *(const float2*)(g_W2T + (size_t)k1 * N_OUT + n2);
        float2 w2 = *(const float2*)(g_W2T + (size_t)k2 * N_OUT + n2);
        float2 w3 = *(const float2*)(g_W2T + (size_t)k3 * N_OUT + n2);
        accx = __fadd_rn(accx, w0.x); accy = __fadd_rn(accy, w0.y);
        accx = __fadd_rn(accx, w1.x); accy = __fadd_rn(accy, w1.y);
        accx = __fadd_rn(accx, w2.x); accy = __fadd_rn(accy, w2.y);
        accx = __fadd_rn(accx, w3.x); accy = __fadd_rn(accy, w3.y);
    }
    for (; j < cnt; j++) {
        int k = sidx[j];
        float2 w = *(const float2*)(g_W2T + (size_t)k * N_OUT + n2);
        accx = __fadd_rn(accx, w.x); accy = __fadd_rn(accy, w.y);
    }

    float2 bb = *(const float2*)(b2 + n2);
    float cx = __fadd_rn(accx, bb.x);
    float cy = __fadd_rn(accy, bb.y);
    float2 mo = *(const float2*)(g_mem2 + (size_t)m * N_OUT + n2);
    float nmx, nmy, spx, spy;
    lif_update(mo.x, cx, nmx, spx);
    lif_update(mo.y, cy, nmy, spy);
    *(float2*)(g_mem2 + (size_t)m * N_OUT + n2) = make_float2(nmx, nmy);
    *(float2*)(out_spk + (size_t)m * N_OUT + n2) = make_float2(spx, spy);
    *(float2*)(out_mem + (size_t)m * N_OUT + n2) = make_float2(nmx, nmy);
}

// ---------------------------------------------------------------------------
// Launch — no __device__ symbol addresses taken on the host.
// ---------------------------------------------------------------------------
extern "C" void kernel_launch(void* const* d_in, const int* in_sizes, int n_in,
                              void* d_out, int out_size) {
    const float* x  = (const float*)d_in[0];
    const float* W1 = (const float*)d_in[1];
    const float* b1 = (const float*)d_in[2];
    const float* W2 = (const float*)d_in[3];
    const float* b2 = (const float*)d_in[4];
    float* out = (float*)d_out;

    init_kernel<<<(BATCH * N_HID + 255) / 256, 256>>>();

    {
        dim3 gT(N_HID / 32, N_OUT / 32);                  // (128, 16)
        transpose_w2_kernel<<<gT, 256>>>(W2);
    }
    {
        dim3 grid(N_HID / 128, (T_STEPS * BATCH) / 128);  // (32, 200)
        gemm1_kernel<<<grid, 256>>>(x, W1, b1);
    }

    float* out_spk_base = out;
    float* out_mem_base = out + (size_t)T_STEPS * BATCH * N_OUT;

    for (int t = 0; t < T_STEPS; t++) {
        step_fused_kernel<<<BATCH, 256>>>(
            t, b2,
            out_spk_base + (size_t)t * BATCH * N_OUT,
            out_mem_base + (size_t)t * BATCH * N_OUT);
    }
}